// round 4
// baseline (speedup 1.0000x reference)
#include <cuda_runtime.h>

#define NB 256      // batch
#define M 128       // txt positions
#define N 128       // img positions (127 real + 1 synthetic fully-padded)
#define D 1024      // embedding dim
#define BK 32       // GEMM k-tile
#define TP 132      // tile pitch (floats), multiple of 4 for float4 alignment
#define NTHREADS 256

__device__ float g_dist[NB];

struct ShMem {
    float A[N * M];     // A[i*M + j] = exp(-2*cost[j,i]) masked
    float Q[N * M];     // working matrix (also reused as GEMM tile staging)
    float invx[M];
    float invy[N];
    float xmask[M];     // 10000 if padded else 0
    float ymask[N];
    float sigma[M];
    float delta[N];
    float spart[NTHREADS];
    float xl, yl;
};

extern __shared__ __align__(16) char smem_raw[];

__global__ __launch_bounds__(NTHREADS, 1)
void ot_kernel(const float* __restrict__ txt,
               const float* __restrict__ obj,
               const int* __restrict__ txt_num,
               const int* __restrict__ obj_num)
{
    ShMem* sh = reinterpret_cast<ShMem*>(smem_raw);
    const int tid  = threadIdx.x;
    const int lane = tid & 31;
    const int warp = tid >> 5;
    const int b    = blockIdx.x;

    const float* txt_b = txt + (size_t)b * M * D;
    const float* obj_b = obj + (size_t)b * M * D;   // img row i -> obj row i+1

    // ---------------- Phase 0: row norms + masks + lengths ----------------
    for (int r = warp; r < 255; r += 8) {
        const float* p = (r < 128) ? (txt_b + r * D) : (obj_b + (r - 127) * D);
        float ss = 0.f;
        #pragma unroll
        for (int k = 0; k < D; k += 128) {
            float4 v = *reinterpret_cast<const float4*>(p + k + lane * 4);
            ss += v.x * v.x + v.y * v.y + v.z * v.z + v.w * v.w;
        }
        #pragma unroll
        for (int o = 16; o; o >>= 1) ss += __shfl_xor_sync(0xffffffffu, ss, o);
        if (lane == 0) {
            float inv = 1.f / fmaxf(sqrtf(ss), 1e-5f);
            if (r < 128) sh->invx[r] = inv;
            else         sh->invy[r - 128] = inv;
        }
    }
    if (tid == 0) sh->invy[127] = 0.f;   // synthetic padded img slot
    if (tid < 128) {
        sh->xmask[tid] = (txt_num[b * 128 + tid] == 0) ? 1e4f : 0.f;
        float ym = 1e4f;
        if (tid < 127) ym = (obj_num[b * 128 + tid + 1] == 0) ? 1e4f : 0.f;
        sh->ymask[tid] = ym;
    }
    __syncthreads();
    if (tid == 0) {
        float c = 0.f;
        for (int j = 0; j < 128; ++j) c += (sh->xmask[j] == 0.f) ? 1.f : 0.f;
        sh->xl = c;
    }
    if (tid == 1) {
        float c = 0.f;
        for (int i = 0; i < 128; ++i) c += (sh->ymask[i] == 0.f) ? 1.f : 0.f;
        sh->yl = c;
    }
    __syncthreads();

    // ---------------- Phase 1: cost GEMM (128x128x1024, fp32) ----------------
    // thread (tx,ty): i = ty*8+ri (img), j = tx*8+cj (txt)
    float* XsT = sh->Q;              // [BK][TP]  (k-major, txt)
    float* YsT = sh->Q + BK * TP;    // [BK][TP]  (k-major, img)
    const int tx = tid & 15, ty = tid >> 4;

    float acc[8][8];
    #pragma unroll
    for (int r = 0; r < 8; ++r)
        #pragma unroll
        for (int c = 0; c < 8; ++c) acc[r][c] = 0.f;

    for (int kb = 0; kb < D; kb += BK) {
        __syncthreads();
        #pragma unroll
        for (int it = 0; it < 4; ++it) {
            int idx = tid + it * 256;          // 0..1023
            int row = idx >> 3;                // 0..127
            int k4  = (idx & 7) * 4;           // 0,4,..,28
            // X tile (txt), normalized
            float4 xv = *reinterpret_cast<const float4*>(txt_b + row * D + kb + k4);
            float sx = sh->invx[row];
            XsT[(k4 + 0) * TP + row] = xv.x * sx;
            XsT[(k4 + 1) * TP + row] = xv.y * sx;
            XsT[(k4 + 2) * TP + row] = xv.z * sx;
            XsT[(k4 + 3) * TP + row] = xv.w * sx;
            // Y tile (img), normalized; row 127 is zero
            float4 yv = make_float4(0.f, 0.f, 0.f, 0.f);
            float sy = sh->invy[row];
            if (row < 127)
                yv = *reinterpret_cast<const float4*>(obj_b + (row + 1) * D + kb + k4);
            YsT[(k4 + 0) * TP + row] = yv.x * sy;
            YsT[(k4 + 1) * TP + row] = yv.y * sy;
            YsT[(k4 + 2) * TP + row] = yv.z * sy;
            YsT[(k4 + 3) * TP + row] = yv.w * sy;
        }
        __syncthreads();
        #pragma unroll 8
        for (int kk = 0; kk < BK; ++kk) {
            float4 a0 = *reinterpret_cast<const float4*>(&YsT[kk * TP + ty * 8]);
            float4 a1 = *reinterpret_cast<const float4*>(&YsT[kk * TP + ty * 8 + 4]);
            float4 b0 = *reinterpret_cast<const float4*>(&XsT[kk * TP + tx * 8]);
            float4 b1 = *reinterpret_cast<const float4*>(&XsT[kk * TP + tx * 8 + 4]);
            float av[8] = {a0.x, a0.y, a0.z, a0.w, a1.x, a1.y, a1.z, a1.w};
            float bv[8] = {b0.x, b0.y, b0.z, b0.w, b1.x, b1.y, b1.z, b1.w};
            #pragma unroll
            for (int r = 0; r < 8; ++r)
                #pragma unroll
                for (int c = 0; c < 8; ++c) acc[r][c] += av[r] * bv[c];
        }
    }
    __syncthreads();   // all tile reads done before overwriting Q region

    // Epilogue: A = mask ? 0 : exp(-cost/beta), beta=0.5; Q = A
    #pragma unroll
    for (int ri = 0; ri < 8; ++ri) {
        int i = ty * 8 + ri;
        float ypad = sh->ymask[i];
        #pragma unroll
        for (int c4 = 0; c4 < 2; ++c4) {
            float tmp[4];
            #pragma unroll
            for (int u = 0; u < 4; ++u) {
                int cj = c4 * 4 + u;
                int j = tx * 8 + cj;
                float cost = 1.f - acc[ri][cj];
                float a = (ypad > 0.f || sh->xmask[j] > 0.f) ? 0.f : expf(-2.f * cost);
                tmp[u] = a;
            }
            float4 a4 = make_float4(tmp[0], tmp[1], tmp[2], tmp[3]);
            int base = i * M + tx * 8 + c4 * 4;
            *reinterpret_cast<float4*>(&sh->A[base]) = a4;
            *reinterpret_cast<float4*>(&sh->Q[base]) = a4;
        }
    }
    __syncthreads();

    // ---------------- Phase 2: IPOT (50 iterations, k=1) ----------------
    const float xl = sh->xl, yl = sh->yl;
    if (tid < 128) sh->sigma[tid] = (sh->xmask[tid] > 0.f) ? 0.f : (1.f / xl);
    __syncthreads();

    for (int t = 0; t < 50; ++t) {
        // (a) r_i = sum_j Q_ij * sigma_j ; delta_i = 1/(yl*r_i + ymask_i)
        float sg0 = sh->sigma[lane];
        float sg1 = sh->sigma[lane + 32];
        float sg2 = sh->sigma[lane + 64];
        float sg3 = sh->sigma[lane + 96];
        for (int i = warp; i < N; i += 8) {
            const float* q = &sh->Q[i * M];
            float s = q[lane] * sg0 + q[lane + 32] * sg1
                    + q[lane + 64] * sg2 + q[lane + 96] * sg3;
            #pragma unroll
            for (int o = 16; o; o >>= 1) s += __shfl_xor_sync(0xffffffffu, s, o);
            if (lane == 0) sh->delta[i] = 1.f / (yl * s + sh->ymask[i]);
        }
        __syncthreads();
        // (b) s_j = sum_i delta_i * Q_ij ; sigma_j = 1/(xl*s_j + xmask_j)
        {
            int j = tid & 127, h = tid >> 7;
            const float* q  = &sh->Q[(h * 64) * M + j];
            const float* dl = &sh->delta[h * 64];
            float s = 0.f;
            #pragma unroll 8
            for (int i = 0; i < 64; ++i) s += dl[i] * q[i * M];
            sh->spart[tid] = s;
        }
        __syncthreads();
        if (tid < 128) {
            float s = sh->spart[tid] + sh->spart[tid + 128];
            sh->sigma[tid] = 1.f / (xl * s + sh->xmask[tid]);
        }
        __syncthreads();
        // (c) Q <- A * delta_i * Q * sigma_j   (skip on last iter: that Q,delta,sigma define final T)
        if (t < 49) {
            #pragma unroll 4
            for (int e = tid; e < N * M; e += NTHREADS) {
                int i = e >> 7;
                int j = e & 127;
                sh->Q[e] *= sh->A[e] * sh->delta[i] * sh->sigma[j];
            }
            __syncthreads();
        }
    }

    // ---------------- Final: dist_b = sum cost_ij * delta_i * Q_ij * sigma_j ----------------
    float local = 0.f;
    for (int e = tid; e < N * M; e += NTHREADS) {
        float a = sh->A[e];
        if (a > 0.f) {
            int i = e >> 7, j = e & 127;
            float cost = -0.5f * logf(a);
            local += cost * sh->delta[i] * sh->Q[e] * sh->sigma[j];
        }
    }
    __syncthreads();
    sh->spart[tid] = local;
    __syncthreads();
    #pragma unroll
    for (int s = 128; s; s >>= 1) {
        if (tid < s) sh->spart[tid] += sh->spart[tid + s];
        __syncthreads();
    }
    if (tid == 0) g_dist[b] = sh->spart[0];
}

__global__ void finalize_kernel(float* __restrict__ out) {
    __shared__ float sm[NB];
    int t = threadIdx.x;
    sm[t] = g_dist[t];
    __syncthreads();
    #pragma unroll
    for (int s = NB / 2; s; s >>= 1) {
        if (t < s) sm[t] += sm[t + s];
        __syncthreads();
    }
    if (t == 0) out[0] = 0.01f * sm[0];
}

extern "C" void kernel_launch(void* const* d_in, const int* in_sizes, int n_in,
                              void* d_out, int out_size) {
    const float* txt = (const float*)d_in[0];   // entitytxt_vec [256,128,1024] f32
    const float* obj = (const float*)d_in[1];   // object_vec    [256,128,1024] f32
    const int*   tn  = (const int*)d_in[2];     // entitytxt_num [256,128] i32
    const int*   on  = (const int*)d_in[3];     // object_num    [256,128] i32

    size_t shbytes = sizeof(ShMem);
    cudaFuncSetAttribute(ot_kernel, cudaFuncAttributeMaxDynamicSharedMemorySize,
                         (int)shbytes);
    ot_kernel<<<NB, NTHREADS, shbytes>>>(txt, obj, tn, on);
    finalize_kernel<<<1, NB>>>((float*)d_out);
}

// round 6
// speedup vs baseline: 1.3089x; 1.3089x over previous
#include <cuda_runtime.h>
#include <cuda_bf16.h>
#include <cstdint>

#define NB 256      // batch
#define M 128       // txt positions (j)
#define N 128       // img positions (i): 127 real + 1 synthetic fully-padded
#define D 1024      // embedding dim
#define NTHREADS 256
#define KBLK 64                   // k-values per tile block (64 bf16 = 128B row)
#define NBLKS (D / KBLK)          // 16
#define TILE_BYTES (128 * 128)    // 128 rows x 64 bf16 = 16KB

__device__ float g_dist[NB];

// ------------------------- helpers -------------------------
__device__ __forceinline__ uint32_t smem_u32(const void* p) {
    uint32_t a;
    asm("{ .reg .u64 t; cvta.to.shared.u64 t, %1; cvt.u32.u64 %0, t; }"
        : "=r"(a) : "l"(p));
    return a;
}
#define SWZ(o) ((o) ^ ((((uint32_t)(o)) >> 3) & 0x70))

__device__ __forceinline__ uint32_t cvt2(float a, float b) {
    __nv_bfloat162 p = __float22bfloat162_rn(make_float2(a, b));
    return *reinterpret_cast<uint32_t*>(&p);
}
__device__ __forceinline__ float fast_exp(float x) {
    float y;
    asm("ex2.approx.f32 %0, %1;" : "=f"(y) : "f"(x * 1.4426950408889634f));
    return y;
}
__device__ __forceinline__ void ldsm_x4(uint32_t addr, uint32_t& r0, uint32_t& r1,
                                        uint32_t& r2, uint32_t& r3) {
    asm volatile("ldmatrix.sync.aligned.m8n8.x4.shared.b16 {%0,%1,%2,%3}, [%4];"
                 : "=r"(r0), "=r"(r1), "=r"(r2), "=r"(r3) : "r"(addr));
}
__device__ __forceinline__ void mma16816(float* c, uint32_t a0, uint32_t a1,
                                         uint32_t a2, uint32_t a3,
                                         uint32_t b0, uint32_t b1) {
    asm volatile(
        "mma.sync.aligned.m16n8k16.row.col.f32.bf16.bf16.f32 "
        "{%0,%1,%2,%3}, {%4,%5,%6,%7}, {%8,%9}, {%0,%1,%2,%3};"
        : "+f"(c[0]), "+f"(c[1]), "+f"(c[2]), "+f"(c[3])
        : "r"(a0), "r"(a1), "r"(a2), "r"(a3), "r"(b0), "r"(b1));
}

struct ShMem {
    float A[N * M];     // A[i*M + j] = exp(-2*cost) masked
    float Q[N * M];
    char  tiles_raw[4 * TILE_BYTES + 1024];   // X0,Y0,X1,Y1 (1024-aligned at runtime)
    float invx[M];
    float invy[N];
    float xmask[M];
    float ymask[N];
    float sigma[M];
    float delta[N];
    float spart[NTHREADS];
    float xl, yl;
};

extern __shared__ __align__(16) char smem_raw[];

__global__ __launch_bounds__(NTHREADS, 1)
void ot_kernel(const float* __restrict__ txt,
               const float* __restrict__ obj,
               const int* __restrict__ txt_num,
               const int* __restrict__ obj_num)
{
    ShMem* sh = reinterpret_cast<ShMem*>(smem_raw);
    const int tid  = threadIdx.x;
    const int lane = tid & 31;
    const int warp = tid >> 5;
    const int b    = blockIdx.x;

    const float* txt_b = txt + (size_t)b * M * D;
    const float* obj_b = obj + (size_t)b * M * D;   // img row i -> obj row i+1

    char* tbase = (char*)(((uintptr_t)sh->tiles_raw + 1023) & ~(uintptr_t)1023);
    const uint32_t tbase_s = (smem_u32(sh->tiles_raw) + 1023u) & ~1023u;

    // ---------------- Phase 0: masks + lengths ----------------
    if (tid < 128) {
        sh->xmask[tid] = (txt_num[b * 128 + tid] == 0) ? 1e4f : 0.f;
        float ym = 1e4f;
        if (tid < 127) ym = (obj_num[b * 128 + tid + 1] == 0) ? 1e4f : 0.f;
        sh->ymask[tid] = ym;
    }
    __syncthreads();
    if (tid == 0) {
        float c = 0.f;
        for (int j = 0; j < 128; ++j) c += (sh->xmask[j] == 0.f) ? 1.f : 0.f;
        sh->xl = c;
    }
    if (tid == 1) {
        float c = 0.f;
        for (int i = 0; i < 128; ++i) c += (sh->ymask[i] == 0.f) ? 1.f : 0.f;
        sh->yl = c;
    }

    // ---------------- Phase 1: GEMM via mma.sync bf16 (HMMA) ----------------
    // Loader mapping: thread -> (row = tid>>1, seg = tid&1), 32 floats per matrix per blk.
    const int row = tid >> 1;
    const int seg = tid & 1;
    const uint32_t st_base = (uint32_t)(row * 128 + seg * 64);
    const float* xsrc0 = txt_b + (size_t)row * D + seg * 32;
    const float* ysrc0 = obj_b + (size_t)(row + 1) * D + seg * 32;  // valid if row<127
    float ssx = 0.f, ssy = 0.f;

    // MMA mapping: warp w -> output rows i in [w*16, w*16+16), all 128 j.
    // acc[nb][q][4]: n-block j base = nb*16 + q*8
    float acc[8][2][4];
    #pragma unroll
    for (int nb = 0; nb < 8; ++nb)
        #pragma unroll
        for (int q = 0; q < 2; ++q)
            #pragma unroll
            for (int c = 0; c < 4; ++c) acc[nb][q][c] = 0.f;

    // ldmatrix lane-address components
    const uint32_t ro = (lane & 7) + (((lane >> 3) & 1) << 3);  // row within 16-blk
    const uint32_t ch = (lane >> 4) << 4;                        // k-half byte offset

    float4 vx[8], vy[8];
    // prefetch block 0
    {
        const float4* sx = reinterpret_cast<const float4*>(xsrc0);
        #pragma unroll
        for (int q = 0; q < 8; ++q) vx[q] = sx[q];
        if (row < 127) {
            const float4* sy = reinterpret_cast<const float4*>(ysrc0);
            #pragma unroll
            for (int q = 0; q < 8; ++q) vy[q] = sy[q];
        } else {
            #pragma unroll
            for (int q = 0; q < 8; ++q) vy[q] = make_float4(0.f, 0.f, 0.f, 0.f);
        }
    }

    for (int blk = 0; blk < NBLKS; ++blk) {
        const int buf = blk & 1;
        char* xt = tbase + (2 * buf)     * TILE_BYTES;
        char* yt = tbase + (2 * buf + 1) * TILE_BYTES;

        // ---- convert + store current block (and accumulate sum-of-squares) ----
        #pragma unroll
        for (int q = 0; q < 8; ++q)
            ssx += vx[q].x * vx[q].x + vx[q].y * vx[q].y + vx[q].z * vx[q].z + vx[q].w * vx[q].w;
        #pragma unroll
        for (int q = 0; q < 8; ++q)
            ssy += vy[q].x * vy[q].x + vy[q].y * vy[q].y + vy[q].z * vy[q].z + vy[q].w * vy[q].w;
        #pragma unroll
        for (int q = 0; q < 4; ++q) {
            float4 a = vx[2 * q], c = vx[2 * q + 1];
            uint4 u = make_uint4(cvt2(a.x, a.y), cvt2(a.z, a.w), cvt2(c.x, c.y), cvt2(c.z, c.w));
            *reinterpret_cast<uint4*>(xt + SWZ(st_base + q * 16)) = u;
        }
        #pragma unroll
        for (int q = 0; q < 4; ++q) {
            float4 a = vy[2 * q], c = vy[2 * q + 1];
            uint4 u = make_uint4(cvt2(a.x, a.y), cvt2(a.z, a.w), cvt2(c.x, c.y), cvt2(c.z, c.w));
            *reinterpret_cast<uint4*>(yt + SWZ(st_base + q * 16)) = u;
        }
        __syncthreads();

        // ---- prefetch next block (overlaps with MMA below) ----
        if (blk + 1 < NBLKS) {
            const float4* sx = reinterpret_cast<const float4*>(xsrc0 + (blk + 1) * KBLK);
            #pragma unroll
            for (int q = 0; q < 8; ++q) vx[q] = sx[q];
            if (row < 127) {
                const float4* sy = reinterpret_cast<const float4*>(ysrc0 + (blk + 1) * KBLK);
                #pragma unroll
                for (int q = 0; q < 8; ++q) vy[q] = sy[q];
            }
        }

        // ---- MMA on this block: Y (rows i) = A operand, X (rows j) = B operand ----
        const uint32_t xs = tbase_s + (2 * buf)     * TILE_BYTES;
        const uint32_t ys = tbase_s + (2 * buf + 1) * TILE_BYTES;
        #pragma unroll
        for (int s = 0; s < 4; ++s) {
            const uint32_t coff = (uint32_t)(s * 32) + ch;
            uint32_t a0, a1, a2, a3;
            ldsm_x4(ys + SWZ((warp * 16 + ro) * 128 + coff), a0, a1, a2, a3);
            #pragma unroll
            for (int nb = 0; nb < 8; ++nb) {
                uint32_t r0, r1, r2, r3;
                ldsm_x4(xs + SWZ((nb * 16 + ro) * 128 + coff), r0, r1, r2, r3);
                mma16816(acc[nb][0], a0, a1, a2, a3, r0, r2);
                mma16816(acc[nb][1], a0, a1, a2, a3, r1, r3);
            }
        }
        // one barrier per block: reuse distance of a buffer is 2 barriers
        if (blk + 1 < NBLKS) __syncthreads();
    }
    __syncthreads();

    // ---------------- norms (fused sum-of-squares reduction) ----------------
    sh->spart[tid] = ssx;
    __syncthreads();
    if (tid < 128)
        sh->invx[tid] = 1.f / fmaxf(sqrtf(sh->spart[2 * tid] + sh->spart[2 * tid + 1]), 1e-5f);
    __syncthreads();
    sh->spart[tid] = ssy;
    __syncthreads();
    if (tid < 128)
        sh->invy[tid] = 1.f / fmaxf(sqrtf(sh->spart[2 * tid] + sh->spart[2 * tid + 1]), 1e-5f);
    __syncthreads();

    // ---------------- Epilogue: acc -> A,Q (A = exp(-2*cost), masked) -------
    {
        const int r = lane >> 2;            // 0..7
        const int cp = (lane & 3) * 2;      // 0,2,4,6
        const int i0 = warp * 16 + r;
        const int i1 = i0 + 8;
        const float iy0 = sh->invy[i0], iy1 = sh->invy[i1];
        const float ym0 = sh->ymask[i0], ym1 = sh->ymask[i1];
        #pragma unroll
        for (int nb = 0; nb < 8; ++nb) {
            #pragma unroll
            for (int q = 0; q < 2; ++q) {
                const int j = nb * 16 + q * 8 + cp;
                const float ix0 = sh->invx[j],  ix1 = sh->invx[j + 1];
                const float xm0 = sh->xmask[j], xm1 = sh->xmask[j + 1];
                const float* c = acc[nb][q];
                float a00 = (ym0 > 0.f || xm0 > 0.f) ? 0.f
                          : fast_exp(-2.f * (1.f - c[0] * iy0 * ix0));
                float a01 = (ym0 > 0.f || xm1 > 0.f) ? 0.f
                          : fast_exp(-2.f * (1.f - c[1] * iy0 * ix1));
                float a10 = (ym1 > 0.f || xm0 > 0.f) ? 0.f
                          : fast_exp(-2.f * (1.f - c[2] * iy1 * ix0));
                float a11 = (ym1 > 0.f || xm1 > 0.f) ? 0.f
                          : fast_exp(-2.f * (1.f - c[3] * iy1 * ix1));
                float2 p0 = make_float2(a00, a01);
                float2 p1 = make_float2(a10, a11);
                *reinterpret_cast<float2*>(&sh->A[i0 * M + j]) = p0;
                *reinterpret_cast<float2*>(&sh->Q[i0 * M + j]) = p0;
                *reinterpret_cast<float2*>(&sh->A[i1 * M + j]) = p1;
                *reinterpret_cast<float2*>(&sh->Q[i1 * M + j]) = p1;
            }
        }
    }
    __syncthreads();

    // ---------------- Phase 2: IPOT (50 iterations, k=1) ----------------
    const float xl = sh->xl, yl = sh->yl;
    if (tid < 128) sh->sigma[tid] = (sh->xmask[tid] > 0.f) ? 0.f : (1.f / xl);
    __syncthreads();

    for (int t = 0; t < 50; ++t) {
        // (a) r_i = sum_j Q_ij * sigma_j ; delta_i = 1/(yl*r_i + ymask_i)
        float sg0 = sh->sigma[lane];
        float sg1 = sh->sigma[lane + 32];
        float sg2 = sh->sigma[lane + 64];
        float sg3 = sh->sigma[lane + 96];
        for (int i = warp; i < N; i += 8) {
            const float* q = &sh->Q[i * M];
            float s = q[lane] * sg0 + q[lane + 32] * sg1
                    + q[lane + 64] * sg2 + q[lane + 96] * sg3;
            #pragma unroll
            for (int o = 16; o; o >>= 1) s += __shfl_xor_sync(0xffffffffu, s, o);
            if (lane == 0) sh->delta[i] = 1.f / (yl * s + sh->ymask[i]);
        }
        __syncthreads();
        // (b) s_j = sum_i delta_i * Q_ij ; sigma_j = 1/(xl*s_j + xmask_j)
        {
            int j = tid & 127, h = tid >> 7;
            const float* q  = &sh->Q[(h * 64) * M + j];
            const float* dl = &sh->delta[h * 64];
            float s = 0.f;
            #pragma unroll 8
            for (int i = 0; i < 64; ++i) s += dl[i] * q[i * M];
            sh->spart[tid] = s;
        }
        __syncthreads();
        if (tid < 128) {
            float s = sh->spart[tid] + sh->spart[tid + 128];
            sh->sigma[tid] = 1.f / (xl * s + sh->xmask[tid]);
        }
        __syncthreads();
        // (c) Q <- A * delta_i * Q * sigma_j (skip last iter), float4-vectorized
        if (t < 49) {
            const float4* Av = reinterpret_cast<const float4*>(sh->A);
            float4*       Qv = reinterpret_cast<float4*>(sh->Q);
            const float4* sv = reinterpret_cast<const float4*>(sh->sigma);
            #pragma unroll 4
            for (int e = tid; e < (N * M) / 4; e += NTHREADS) {
                int i = e >> 5;
                float dl = sh->delta[i];
                float4 s4 = sv[e & 31];
                float4 qv = Qv[e], av = Av[e];
                qv.x *= av.x * dl * s4.x;
                qv.y *= av.y * dl * s4.y;
                qv.z *= av.z * dl * s4.z;
                qv.w *= av.w * dl * s4.w;
                Qv[e] = qv;
            }
            __syncthreads();
        }
    }

    // ---------------- Final: dist_b = sum cost_ij * delta_i * Q_ij * sigma_j --
    float local = 0.f;
    for (int e = tid; e < N * M; e += NTHREADS) {
        float a = sh->A[e];
        if (a > 0.f) {
            int i = e >> 7, j = e & 127;
            float cost = -0.5f * logf(a);
            local += cost * sh->delta[i] * sh->Q[e] * sh->sigma[j];
        }
    }
    __syncthreads();
    sh->spart[tid] = local;
    __syncthreads();
    #pragma unroll
    for (int s = 128; s; s >>= 1) {
        if (tid < s) sh->spart[tid] += sh->spart[tid + s];
        __syncthreads();
    }
    if (tid == 0) g_dist[b] = sh->spart[0];
}

__global__ void finalize_kernel(float* __restrict__ out) {
    __shared__ float sm[NB];
    int t = threadIdx.x;
    sm[t] = g_dist[t];
    __syncthreads();
    #pragma unroll
    for (int s = NB / 2; s; s >>= 1) {
        if (t < s) sm[t] += sm[t + s];
        __syncthreads();
    }
    if (t == 0) out[0] = 0.01f * sm[0];
}

extern "C" void kernel_launch(void* const* d_in, const int* in_sizes, int n_in,
                              void* d_out, int out_size) {
    const float* txt = (const float*)d_in[0];   // entitytxt_vec [256,128,1024] f32
    const float* obj = (const float*)d_in[1];   // object_vec    [256,128,1024] f32
    const int*   tn  = (const int*)d_in[2];     // entitytxt_num [256,128] i32
    const int*   on  = (const int*)d_in[3];     // object_num    [256,128] i32

    size_t shbytes = sizeof(ShMem);
    cudaFuncSetAttribute(ot_kernel, cudaFuncAttributeMaxDynamicSharedMemorySize,
                         (int)shbytes);
    ot_kernel<<<NB, NTHREADS, shbytes>>>(txt, obj, tn, on);
    finalize_kernel<<<1, NB>>>((float*)d_out);
}

// round 7
// speedup vs baseline: 3.3452x; 2.5558x over previous
#include <cuda_runtime.h>
#include <cuda_bf16.h>
#include <cstdint>

#define NB 256      // batch
#define M 128       // txt positions (j)
#define N 128       // img positions (i): 127 real + 1 synthetic fully-padded
#define D 1024      // embedding dim
#define NTHREADS 256
#define KBLK 32                   // k-values per tile block (32 bf16 = 64B row)
#define NBLKS (D / KBLK)          // 32
#define TILE_B (128 * 64)         // 128 rows x 64B = 8KB per matrix per buffer

__device__ float g_dist[NB];
__device__ unsigned int g_count = 0;

// ------------------------- helpers -------------------------
__device__ __forceinline__ uint32_t smem_u32(const void* p) {
    uint32_t a;
    asm("{ .reg .u64 t; cvta.to.shared.u64 t, %1; cvt.u32.u64 %0, t; }"
        : "=r"(a) : "l"(p));
    return a;
}
#define SWZ64(o) ((o) ^ ((((uint32_t)(o)) >> 3) & 0x30))

__device__ __forceinline__ uint32_t cvt2(float a, float b) {
    __nv_bfloat162 p = __float22bfloat162_rn(make_float2(a, b));
    return *reinterpret_cast<uint32_t*>(&p);
}
__device__ __forceinline__ float fast_exp(float x) {
    float y;
    asm("ex2.approx.f32 %0, %1;" : "=f"(y) : "f"(x * 1.4426950408889634f));
    return y;
}
__device__ __forceinline__ void ldsm_x4(uint32_t addr, uint32_t& r0, uint32_t& r1,
                                        uint32_t& r2, uint32_t& r3) {
    asm volatile("ldmatrix.sync.aligned.m8n8.x4.shared.b16 {%0,%1,%2,%3}, [%4];"
                 : "=r"(r0), "=r"(r1), "=r"(r2), "=r"(r3) : "r"(addr));
}
__device__ __forceinline__ void mma16816(float* c, uint32_t a0, uint32_t a1,
                                         uint32_t a2, uint32_t a3,
                                         uint32_t b0, uint32_t b1) {
    asm volatile(
        "mma.sync.aligned.m16n8k16.row.col.f32.bf16.bf16.f32 "
        "{%0,%1,%2,%3}, {%4,%5,%6,%7}, {%8,%9}, {%0,%1,%2,%3};"
        : "+f"(c[0]), "+f"(c[1]), "+f"(c[2]), "+f"(c[3])
        : "r"(a0), "r"(a1), "r"(a2), "r"(a3), "r"(b0), "r"(b1));
}

struct ShMem {
    float Q[N * M];        // 64KB; GEMM k-tiles are aliased into the front of this
    float invx[M];
    float invy[N];
    float xmask[M];
    float ymask[N];
    float sigma[M];        // read as float4
    float delta[N];
    float rvec[N];
    float spart[NTHREADS];
    float xl, yl;
    unsigned int tick;
    unsigned int pad;
};

extern __shared__ __align__(16) char smem_raw[];

__global__ __launch_bounds__(NTHREADS, 2)
void ot_kernel(const float* __restrict__ txt,
               const float* __restrict__ obj,
               const int* __restrict__ txt_num,
               const int* __restrict__ obj_num,
               float* __restrict__ out)
{
    ShMem* sh = reinterpret_cast<ShMem*>(smem_raw);
    const int tid  = threadIdx.x;
    const int lane = tid & 31;
    const int warp = tid >> 5;
    const int b    = blockIdx.x;

    const float* txt_b = txt + (size_t)b * M * D;
    const float* obj_b = obj + (size_t)b * M * D;   // img row i -> obj row i+1

    // GEMM tiles live inside the (not-yet-used) Q region, 1024-aligned
    char* tbase = (char*)(((uintptr_t)sh->Q + 1023) & ~(uintptr_t)1023);
    const uint32_t tbase_s = (smem_u32(sh->Q) + 1023u) & ~1023u;

    // ---------------- Phase 0: masks + lengths ----------------
    if (tid < 128) {
        sh->xmask[tid] = (txt_num[b * 128 + tid] == 0) ? 1e4f : 0.f;
        float ym = 1e4f;
        if (tid < 127) ym = (obj_num[b * 128 + tid + 1] == 0) ? 1e4f : 0.f;
        sh->ymask[tid] = ym;
    }
    __syncthreads();
    if (tid == 0) {
        float c = 0.f;
        for (int j = 0; j < 128; ++j) c += (sh->xmask[j] == 0.f) ? 1.f : 0.f;
        sh->xl = c;
    }
    if (tid == 1) {
        float c = 0.f;
        for (int i = 0; i < 128; ++i) c += (sh->ymask[i] == 0.f) ? 1.f : 0.f;
        sh->yl = c;
    }

    // ---------------- Phase 1: GEMM via mma.sync bf16 (HMMA) ----------------
    // Loader: thread -> (row = tid>>1, half = tid&1): 16 floats per matrix per blk
    const int row  = tid >> 1;
    const int half = tid & 1;
    const uint32_t st_off = (uint32_t)(row * 64 + half * 32);
    const float* xsrc0 = txt_b + (size_t)row * D + half * 16;
    const float* ysrc0 = obj_b + (size_t)(row + 1) * D + half * 16;  // valid if row<127
    float ssx = 0.f, ssy = 0.f;

    // MMA warp grid 4x2: wi -> 32 i-rows, wj -> 64 j-cols
    const int wi = warp >> 1;
    const int wj = warp & 1;
    float acc[2][4][2][4];   // [mi][nb][q][4]
    #pragma unroll
    for (int mi = 0; mi < 2; ++mi)
        #pragma unroll
        for (int nb = 0; nb < 4; ++nb)
            #pragma unroll
            for (int q = 0; q < 2; ++q)
                #pragma unroll
                for (int c = 0; c < 4; ++c) acc[mi][nb][q][c] = 0.f;

    const uint32_t ro = (lane & 7) + (((lane >> 3) & 1) << 3);
    const uint32_t ch = (lane >> 4) << 4;

    for (int blk = 0; blk < NBLKS; ++blk) {
        const int buf = blk & 1;
        char* xt = tbase + buf * (2 * TILE_B);
        char* yt = xt + TILE_B;

        // ---- load + convert + store (sum-of-squares fused) ----
        {
            float4 v[4];
            const float4* sx = reinterpret_cast<const float4*>(xsrc0 + blk * KBLK);
            #pragma unroll
            for (int q = 0; q < 4; ++q) v[q] = sx[q];
            #pragma unroll
            for (int q = 0; q < 4; ++q)
                ssx += v[q].x * v[q].x + v[q].y * v[q].y + v[q].z * v[q].z + v[q].w * v[q].w;
            uint4 u0 = make_uint4(cvt2(v[0].x, v[0].y), cvt2(v[0].z, v[0].w),
                                  cvt2(v[1].x, v[1].y), cvt2(v[1].z, v[1].w));
            uint4 u1 = make_uint4(cvt2(v[2].x, v[2].y), cvt2(v[2].z, v[2].w),
                                  cvt2(v[3].x, v[3].y), cvt2(v[3].z, v[3].w));
            *reinterpret_cast<uint4*>(xt + SWZ64(st_off))      = u0;
            *reinterpret_cast<uint4*>(xt + SWZ64(st_off + 16)) = u1;
        }
        {
            float4 v[4];
            if (row < 127) {
                const float4* sy = reinterpret_cast<const float4*>(ysrc0 + blk * KBLK);
                #pragma unroll
                for (int q = 0; q < 4; ++q) v[q] = sy[q];
            } else {
                #pragma unroll
                for (int q = 0; q < 4; ++q) v[q] = make_float4(0.f, 0.f, 0.f, 0.f);
            }
            #pragma unroll
            for (int q = 0; q < 4; ++q)
                ssy += v[q].x * v[q].x + v[q].y * v[q].y + v[q].z * v[q].z + v[q].w * v[q].w;
            uint4 u0 = make_uint4(cvt2(v[0].x, v[0].y), cvt2(v[0].z, v[0].w),
                                  cvt2(v[1].x, v[1].y), cvt2(v[1].z, v[1].w));
            uint4 u1 = make_uint4(cvt2(v[2].x, v[2].y), cvt2(v[2].z, v[2].w),
                                  cvt2(v[3].x, v[3].y), cvt2(v[3].z, v[3].w));
            *reinterpret_cast<uint4*>(yt + SWZ64(st_off))      = u0;
            *reinterpret_cast<uint4*>(yt + SWZ64(st_off + 16)) = u1;
        }
        __syncthreads();

        // ---- MMA: Y rows (i) = A operand, X rows (j) = B operand ----
        const uint32_t xs = tbase_s + buf * (2 * TILE_B);
        const uint32_t ys = xs + TILE_B;
        #pragma unroll
        for (int s = 0; s < 2; ++s) {
            const uint32_t coff = (uint32_t)(s * 32) + ch;
            uint32_t a[2][4];
            #pragma unroll
            for (int mi = 0; mi < 2; ++mi)
                ldsm_x4(ys + SWZ64((wi * 32 + mi * 16 + ro) * 64 + coff),
                        a[mi][0], a[mi][1], a[mi][2], a[mi][3]);
            #pragma unroll
            for (int nb = 0; nb < 4; ++nb) {
                uint32_t r0, r1, r2, r3;
                ldsm_x4(xs + SWZ64((wj * 64 + nb * 16 + ro) * 64 + coff),
                        r0, r1, r2, r3);
                #pragma unroll
                for (int mi = 0; mi < 2; ++mi) {
                    mma16816(acc[mi][nb][0], a[mi][0], a[mi][1], a[mi][2], a[mi][3], r0, r2);
                    mma16816(acc[mi][nb][1], a[mi][0], a[mi][1], a[mi][2], a[mi][3], r1, r3);
                }
            }
        }
        if (blk + 1 < NBLKS) __syncthreads();
    }
    __syncthreads();

    // ---------------- norms ----------------
    sh->spart[tid] = ssx;
    __syncthreads();
    if (tid < 128)
        sh->invx[tid] = 1.f / fmaxf(sqrtf(sh->spart[2 * tid] + sh->spart[2 * tid + 1]), 1e-5f);
    __syncthreads();
    sh->spart[tid] = ssy;
    __syncthreads();
    if (tid < 128)
        sh->invy[tid] = 1.f / fmaxf(sqrtf(sh->spart[2 * tid] + sh->spart[2 * tid + 1]), 1e-5f);
    __syncthreads();

    // ---------------- Epilogue: acc -> Q (= A = exp(-2*cost), masked) -------
    {
        const int r  = lane >> 2;
        const int cp = (lane & 3) * 2;
        #pragma unroll
        for (int mi = 0; mi < 2; ++mi) {
            const int i0 = wi * 32 + mi * 16 + r;
            const int i1 = i0 + 8;
            const float iy0 = sh->invy[i0], iy1 = sh->invy[i1];
            const float ym0 = sh->ymask[i0], ym1 = sh->ymask[i1];
            #pragma unroll
            for (int nb = 0; nb < 4; ++nb) {
                #pragma unroll
                for (int q = 0; q < 2; ++q) {
                    const int j = wj * 64 + nb * 16 + q * 8 + cp;
                    const float ix0 = sh->invx[j],  ix1 = sh->invx[j + 1];
                    const float xm0 = sh->xmask[j], xm1 = sh->xmask[j + 1];
                    const float* c = acc[mi][nb][q];
                    float a00 = (ym0 > 0.f || xm0 > 0.f) ? 0.f
                              : fast_exp(-2.f * (1.f - c[0] * iy0 * ix0));
                    float a01 = (ym0 > 0.f || xm1 > 0.f) ? 0.f
                              : fast_exp(-2.f * (1.f - c[1] * iy0 * ix1));
                    float a10 = (ym1 > 0.f || xm0 > 0.f) ? 0.f
                              : fast_exp(-2.f * (1.f - c[2] * iy1 * ix0));
                    float a11 = (ym1 > 0.f || xm1 > 0.f) ? 0.f
                              : fast_exp(-2.f * (1.f - c[3] * iy1 * ix1));
                    *reinterpret_cast<float2*>(&sh->Q[i0 * M + j]) = make_float2(a00, a01);
                    *reinterpret_cast<float2*>(&sh->Q[i1 * M + j]) = make_float2(a10, a11);
                }
            }
        }
    }
    __syncthreads();

    // ---------------- A into registers (linear float4 mapping) ----------------
    // thread owns float4 elements e4 = tid + 256*k, k=0..15:
    //   i = (tid>>5) + 8k, j4 = tid&31  (j = 4*j4 .. 4*j4+3)
    float4 A4[16];
    {
        const float4* Qv = reinterpret_cast<const float4*>(sh->Q);
        #pragma unroll
        for (int k = 0; k < 16; ++k) A4[k] = Qv[tid + 256 * k];
    }

    // ---------------- Phase 2: IPOT ----------------
    const float xl = sh->xl, yl = sh->yl;
    const float4* sigv = reinterpret_cast<const float4*>(sh->sigma);
    const int j4 = tid & 31;
    const int ib = tid >> 5;

    if (tid < 128) sh->sigma[tid] = (sh->xmask[tid] > 0.f) ? 0.f : (1.f / xl);
    __syncthreads();

    // r0 = A . sigma0  (from registers)
    {
        float4 sg = sigv[j4];
        #pragma unroll
        for (int k = 0; k < 16; ++k) {
            float4 a = A4[k];
            float p = a.x * sg.x + a.y * sg.y + a.z * sg.z + a.w * sg.w;
            #pragma unroll
            for (int o = 16; o; o >>= 1) p += __shfl_xor_sync(0xffffffffu, p, o);
            if (lane == 0) sh->rvec[ib + 8 * k] = p;
        }
    }
    __syncthreads();

    for (int t = 0; t < 50; ++t) {
        // delta_i = 1/(yl*r_i + ymask_i)
        if (tid < 128)
            sh->delta[tid] = 1.f / (yl * sh->rvec[tid] + sh->ymask[tid]);
        __syncthreads();
        // (b) s_j = sum_i delta_i * Q_ij
        {
            int j = tid & 127, h = tid >> 7;
            const float* q  = &sh->Q[(h * 64) * M + j];
            const float* dl = &sh->delta[h * 64];
            float s = 0.f;
            #pragma unroll 8
            for (int i = 0; i < 64; ++i) s += dl[i] * q[i * M];
            sh->spart[tid] = s;
        }
        __syncthreads();
        if (tid < 128) {
            float s = sh->spart[tid] + sh->spart[tid + 128];
            sh->sigma[tid] = 1.f / (xl * s + sh->xmask[tid]);
        }
        __syncthreads();
        // (c) Q <- A*delta_i*Q*sigma_j, fused with next r_i = sum_j Q_new*sigma_j
        if (t < 49) {
            float4* Qv = reinterpret_cast<float4*>(sh->Q);
            float4 sg = sigv[j4];
            #pragma unroll
            for (int k = 0; k < 16; ++k) {
                const int i = ib + 8 * k;
                const float dl = sh->delta[i];
                float4 q = Qv[tid + 256 * k];
                float4 a = A4[k];
                q.x *= a.x * dl * sg.x;
                q.y *= a.y * dl * sg.y;
                q.z *= a.z * dl * sg.z;
                q.w *= a.w * dl * sg.w;
                Qv[tid + 256 * k] = q;
                float p = q.x * sg.x + q.y * sg.y + q.z * sg.z + q.w * sg.w;
                #pragma unroll
                for (int o = 16; o; o >>= 1) p += __shfl_xor_sync(0xffffffffu, p, o);
                if (lane == 0) sh->rvec[i] = p;
            }
            __syncthreads();
        }
    }

    // ---------------- Final: dist_b = sum cost * delta_i * Q * sigma_j ----------
    float local = 0.f;
    {
        const float4* Qv = reinterpret_cast<const float4*>(sh->Q);
        float4 sg = sigv[j4];
        #pragma unroll
        for (int k = 0; k < 16; ++k) {
            const int i = ib + 8 * k;
            const float dl = sh->delta[i];
            float4 q = Qv[tid + 256 * k];
            float4 a = A4[k];
            if (a.x > 0.f) local += (-0.5f * __logf(a.x)) * dl * q.x * sg.x;
            if (a.y > 0.f) local += (-0.5f * __logf(a.y)) * dl * q.y * sg.y;
            if (a.z > 0.f) local += (-0.5f * __logf(a.z)) * dl * q.z * sg.z;
            if (a.w > 0.f) local += (-0.5f * __logf(a.w)) * dl * q.w * sg.w;
        }
    }
    __syncthreads();
    sh->spart[tid] = local;
    __syncthreads();
    #pragma unroll
    for (int s = 128; s; s >>= 1) {
        if (tid < s) sh->spart[tid] += sh->spart[tid + s];
        __syncthreads();
    }
    if (tid == 0) g_dist[b] = sh->spart[0];

    // ---------------- last block reduces g_dist -> out ----------------
    __threadfence();
    if (tid == 0) sh->tick = atomicAdd(&g_count, 1u);
    __syncthreads();
    if (sh->tick == NB - 1) {
        __threadfence();
        sh->spart[tid] = g_dist[tid];
        __syncthreads();
        #pragma unroll
        for (int s = 128; s; s >>= 1) {
            if (tid < s) sh->spart[tid] += sh->spart[tid + s];
            __syncthreads();
        }
        if (tid == 0) {
            out[0] = 0.01f * sh->spart[0];
            g_count = 0;   // reset for next (graph-replayed) call
        }
    }
}

extern "C" void kernel_launch(void* const* d_in, const int* in_sizes, int n_in,
                              void* d_out, int out_size) {
    const float* txt = (const float*)d_in[0];   // entitytxt_vec [256,128,1024] f32
    const float* obj = (const float*)d_in[1];   // object_vec    [256,128,1024] f32
    const int*   tn  = (const int*)d_in[2];     // entitytxt_num [256,128] i32
    const int*   on  = (const int*)d_in[3];     // object_num    [256,128] i32

    size_t shbytes = sizeof(ShMem);
    cudaFuncSetAttribute(ot_kernel, cudaFuncAttributeMaxDynamicSharedMemorySize,
                         (int)shbytes);
    ot_kernel<<<NB, NTHREADS, shbytes>>>(txt, obj, tn, on, (float*)d_out);
}

// round 8
// speedup vs baseline: 4.8084x; 1.4374x over previous
#include <cuda_runtime.h>
#include <cuda_bf16.h>
#include <cstdint>

#define NB 256      // batch
#define M 128       // txt positions (j)
#define N 128       // img positions (i): 127 real + 1 synthetic fully-padded
#define D 1024      // embedding dim
#define NTHREADS 256
#define KBLK 32                   // k-values per tile block (32 bf16 = 64B row)
#define NBLKS (D / KBLK)          // 32
#define TILE_B (128 * 64)         // 8KB per matrix per buffer

typedef unsigned long long u64;

__device__ float g_dist[NB];
__device__ unsigned int g_count = 0;

// ------------------------- helpers -------------------------
__device__ __forceinline__ uint32_t smem_u32(const void* p) {
    uint32_t a;
    asm("{ .reg .u64 t; cvta.to.shared.u64 t, %1; cvt.u32.u64 %0, t; }"
        : "=r"(a) : "l"(p));
    return a;
}
#define SWZ64(o) ((o) ^ ((((uint32_t)(o)) >> 3) & 0x30))

__device__ __forceinline__ uint32_t cvt2(float a, float b) {
    __nv_bfloat162 p = __float22bfloat162_rn(make_float2(a, b));
    return *reinterpret_cast<uint32_t*>(&p);
}
__device__ __forceinline__ float fast_exp(float x) {
    float y;
    asm("ex2.approx.f32 %0, %1;" : "=f"(y) : "f"(x * 1.4426950408889634f));
    return y;
}
__device__ __forceinline__ void ldsm_x4(uint32_t addr, uint32_t& r0, uint32_t& r1,
                                        uint32_t& r2, uint32_t& r3) {
    asm volatile("ldmatrix.sync.aligned.m8n8.x4.shared.b16 {%0,%1,%2,%3}, [%4];"
                 : "=r"(r0), "=r"(r1), "=r"(r2), "=r"(r3) : "r"(addr));
}
__device__ __forceinline__ void mma16816(float* c, uint32_t a0, uint32_t a1,
                                         uint32_t a2, uint32_t a3,
                                         uint32_t b0, uint32_t b1) {
    asm volatile(
        "mma.sync.aligned.m16n8k16.row.col.f32.bf16.bf16.f32 "
        "{%0,%1,%2,%3}, {%4,%5,%6,%7}, {%8,%9}, {%0,%1,%2,%3};"
        : "+f"(c[0]), "+f"(c[1]), "+f"(c[2]), "+f"(c[3])
        : "r"(a0), "r"(a1), "r"(a2), "r"(a3), "r"(b0), "r"(b1));
}

// ---- packed f32x2 (sm_100+ base ISA) ----
__device__ __forceinline__ u64 pack2(float x, float y) {
    u64 r; asm("mov.b64 %0, {%1, %2};" : "=l"(r) : "f"(x), "f"(y)); return r;
}
__device__ __forceinline__ float2 unpack2(u64 v) {
    float2 r; asm("mov.b64 {%0, %1}, %2;" : "=f"(r.x), "=f"(r.y) : "l"(v)); return r;
}
__device__ __forceinline__ u64 mul2(u64 a, u64 b) {
    u64 d; asm("mul.rn.f32x2 %0, %1, %2;" : "=l"(d) : "l"(a), "l"(b)); return d;
}
__device__ __forceinline__ u64 fma2_(u64 a, u64 b, u64 c) {
    u64 d; asm("fma.rn.f32x2 %0, %1, %2, %3;" : "=l"(d) : "l"(a), "l"(b), "l"(c)); return d;
}

union F4U2 { float4 f4; u64 u2[2]; };

// A ownership-linear layout index (in floats):
// thread (warp w, lane = jg + 16*ig) owns i = w*16 + ig*8 + ii, j = jg*8 .. +7
#define AIDX(w, ii, half, ig, jg) \
    (((((w) * 8 + (ii)) * 2 + (half)) * 2 + (ig)) * 16 + (jg)) * 4

struct ShMem {
    float As[N * M];        // 64KB ownership-linear A; GEMM k-tiles aliased inside
    float spartW[8][128];   // per-warp s_j partials
    float spart[NTHREADS];
    float invx[M];
    float invy[N];
    float xmask[M];
    float ymask[N];
    float sigma[M];
    float xl, yl;
    unsigned int tick;
};

extern __shared__ __align__(16) char smem_raw[];

__global__ __launch_bounds__(NTHREADS, 2)
void ot_kernel(const float* __restrict__ txt,
               const float* __restrict__ obj,
               const int* __restrict__ txt_num,
               const int* __restrict__ obj_num,
               float* __restrict__ out)
{
    ShMem* sh = reinterpret_cast<ShMem*>(smem_raw);
    const int tid  = threadIdx.x;
    const int lane = tid & 31;
    const int warp = tid >> 5;
    const int b    = blockIdx.x;

    const float* txt_b = txt + (size_t)b * M * D;
    const float* obj_b = obj + (size_t)b * M * D;   // img row i -> obj row i+1

    // GEMM tiles aliased into the (not-yet-used) As region, 1024-aligned
    char* tbase = (char*)(((uintptr_t)sh->As + 1023) & ~(uintptr_t)1023);
    const uint32_t tbase_s = (smem_u32(sh->As) + 1023u) & ~1023u;

    // ---------------- Phase 0: masks + lengths ----------------
    if (tid < 128) {
        sh->xmask[tid] = (txt_num[b * 128 + tid] == 0) ? 1e4f : 0.f;
        float ym = 1e4f;
        if (tid < 127) ym = (obj_num[b * 128 + tid + 1] == 0) ? 1e4f : 0.f;
        sh->ymask[tid] = ym;
    }
    __syncthreads();
    if (tid == 0) {
        float c = 0.f;
        for (int j = 0; j < 128; ++j) c += (sh->xmask[j] == 0.f) ? 1.f : 0.f;
        sh->xl = c;
    }
    if (tid == 1) {
        float c = 0.f;
        for (int i = 0; i < 128; ++i) c += (sh->ymask[i] == 0.f) ? 1.f : 0.f;
        sh->yl = c;
    }

    // ---------------- Phase 1: GEMM via mma.sync bf16 (HMMA) ----------------
    const int row  = tid >> 1;
    const int half = tid & 1;
    const uint32_t st_off = (uint32_t)(row * 64 + half * 32);
    const float* xsrc0 = txt_b + (size_t)row * D + half * 16;
    const float* ysrc0 = obj_b + (size_t)(row + 1) * D + half * 16;  // valid if row<127
    float ssx = 0.f, ssy = 0.f;

    const int wi = warp >> 1;
    const int wj = warp & 1;
    float acc[2][4][2][4];
    #pragma unroll
    for (int mi = 0; mi < 2; ++mi)
        #pragma unroll
        for (int nb = 0; nb < 4; ++nb)
            #pragma unroll
            for (int q = 0; q < 2; ++q)
                #pragma unroll
                for (int c = 0; c < 4; ++c) acc[mi][nb][q][c] = 0.f;

    const uint32_t ro = (lane & 7) + (((lane >> 3) & 1) << 3);
    const uint32_t ch = (lane >> 4) << 4;

    float4 vx[4], vy[4];
    {   // prefetch block 0
        const float4* sx = reinterpret_cast<const float4*>(xsrc0);
        #pragma unroll
        for (int q = 0; q < 4; ++q) vx[q] = sx[q];
        if (row < 127) {
            const float4* sy = reinterpret_cast<const float4*>(ysrc0);
            #pragma unroll
            for (int q = 0; q < 4; ++q) vy[q] = sy[q];
        } else {
            #pragma unroll
            for (int q = 0; q < 4; ++q) vy[q] = make_float4(0.f, 0.f, 0.f, 0.f);
        }
    }

    for (int blk = 0; blk < NBLKS; ++blk) {
        const int buf = blk & 1;
        char* xt = tbase + buf * (2 * TILE_B);
        char* yt = xt + TILE_B;

        // ---- convert + store (sum-of-squares fused) ----
        #pragma unroll
        for (int q = 0; q < 4; ++q)
            ssx += vx[q].x * vx[q].x + vx[q].y * vx[q].y + vx[q].z * vx[q].z + vx[q].w * vx[q].w;
        #pragma unroll
        for (int q = 0; q < 4; ++q)
            ssy += vy[q].x * vy[q].x + vy[q].y * vy[q].y + vy[q].z * vy[q].z + vy[q].w * vy[q].w;
        {
            uint4 u0 = make_uint4(cvt2(vx[0].x, vx[0].y), cvt2(vx[0].z, vx[0].w),
                                  cvt2(vx[1].x, vx[1].y), cvt2(vx[1].z, vx[1].w));
            uint4 u1 = make_uint4(cvt2(vx[2].x, vx[2].y), cvt2(vx[2].z, vx[2].w),
                                  cvt2(vx[3].x, vx[3].y), cvt2(vx[3].z, vx[3].w));
            *reinterpret_cast<uint4*>(xt + SWZ64(st_off))      = u0;
            *reinterpret_cast<uint4*>(xt + SWZ64(st_off + 16)) = u1;
            uint4 w0 = make_uint4(cvt2(vy[0].x, vy[0].y), cvt2(vy[0].z, vy[0].w),
                                  cvt2(vy[1].x, vy[1].y), cvt2(vy[1].z, vy[1].w));
            uint4 w1 = make_uint4(cvt2(vy[2].x, vy[2].y), cvt2(vy[2].z, vy[2].w),
                                  cvt2(vy[3].x, vy[3].y), cvt2(vy[3].z, vy[3].w));
            *reinterpret_cast<uint4*>(yt + SWZ64(st_off))      = w0;
            *reinterpret_cast<uint4*>(yt + SWZ64(st_off + 16)) = w1;
        }
        // ---- prefetch next block before the barrier (overlaps bar + MMA) ----
        if (blk + 1 < NBLKS) {
            const float4* sx = reinterpret_cast<const float4*>(xsrc0 + (blk + 1) * KBLK);
            #pragma unroll
            for (int q = 0; q < 4; ++q) vx[q] = sx[q];
            if (row < 127) {
                const float4* sy = reinterpret_cast<const float4*>(ysrc0 + (blk + 1) * KBLK);
                #pragma unroll
                for (int q = 0; q < 4; ++q) vy[q] = sy[q];
            }
        }
        __syncthreads();

        // ---- MMA: Y rows (i) = A operand, X rows (j) = B operand ----
        const uint32_t xs = tbase_s + buf * (2 * TILE_B);
        const uint32_t ys = xs + TILE_B;
        #pragma unroll
        for (int s = 0; s < 2; ++s) {
            const uint32_t coff = (uint32_t)(s * 32) + ch;
            uint32_t a[2][4];
            #pragma unroll
            for (int mi = 0; mi < 2; ++mi)
                ldsm_x4(ys + SWZ64((wi * 32 + mi * 16 + ro) * 64 + coff),
                        a[mi][0], a[mi][1], a[mi][2], a[mi][3]);
            #pragma unroll
            for (int nb = 0; nb < 4; ++nb) {
                uint32_t r0, r1, r2, r3;
                ldsm_x4(xs + SWZ64((wj * 64 + nb * 16 + ro) * 64 + coff),
                        r0, r1, r2, r3);
                #pragma unroll
                for (int mi = 0; mi < 2; ++mi) {
                    mma16816(acc[mi][nb][0], a[mi][0], a[mi][1], a[mi][2], a[mi][3], r0, r2);
                    mma16816(acc[mi][nb][1], a[mi][0], a[mi][1], a[mi][2], a[mi][3], r1, r3);
                }
            }
        }
    }
    __syncthreads();

    // ---------------- norms ----------------
    sh->spart[tid] = ssx;
    __syncthreads();
    if (tid < 128)
        sh->invx[tid] = 1.f / fmaxf(sqrtf(sh->spart[2 * tid] + sh->spart[2 * tid + 1]), 1e-5f);
    __syncthreads();
    sh->spart[tid] = ssy;
    __syncthreads();
    if (tid < 128)
        sh->invy[tid] = 1.f / fmaxf(sqrtf(sh->spart[2 * tid] + sh->spart[2 * tid + 1]), 1e-5f);
    __syncthreads();

    // ---------------- Epilogue: acc -> As (ownership-linear layout) ----------
    {
        const int r_ = lane >> 2;
        const int cp = (lane & 3) * 2;
        #pragma unroll
        for (int mi = 0; mi < 2; ++mi) {
            const int i0 = wi * 32 + mi * 16 + r_;
            const int i1 = i0 + 8;
            const int we = i0 >> 4;
            const int ie = i0 & 7;
            const float iy0 = sh->invy[i0], iy1 = sh->invy[i1];
            const float ym0 = sh->ymask[i0], ym1 = sh->ymask[i1];
            #pragma unroll
            for (int nb = 0; nb < 4; ++nb) {
                #pragma unroll
                for (int q = 0; q < 2; ++q) {
                    const int j = wj * 64 + nb * 16 + q * 8 + cp;
                    const int jge = j >> 3, hfe = (j >> 2) & 1, ue = j & 3;
                    const float ix0 = sh->invx[j],  ix1 = sh->invx[j + 1];
                    const float xm0 = sh->xmask[j], xm1 = sh->xmask[j + 1];
                    const float* c = acc[mi][nb][q];
                    float a00 = (ym0 > 0.f || xm0 > 0.f) ? 0.f
                              : fast_exp(-2.f * (1.f - c[0] * iy0 * ix0));
                    float a01 = (ym0 > 0.f || xm1 > 0.f) ? 0.f
                              : fast_exp(-2.f * (1.f - c[1] * iy0 * ix1));
                    float a10 = (ym1 > 0.f || xm0 > 0.f) ? 0.f
                              : fast_exp(-2.f * (1.f - c[2] * iy1 * ix0));
                    float a11 = (ym1 > 0.f || xm1 > 0.f) ? 0.f
                              : fast_exp(-2.f * (1.f - c[3] * iy1 * ix1));
                    *reinterpret_cast<float2*>(&sh->As[AIDX(we, ie, hfe, 0, jge) + ue])
                        = make_float2(a00, a01);
                    *reinterpret_cast<float2*>(&sh->As[AIDX(we, ie, hfe, 1, jge) + ue])
                        = make_float2(a10, a11);
                }
            }
        }
    }
    __syncthreads();

    // ---------------- Phase 2: IPOT with Q in registers ----------------
    const int jg = lane & 15;
    const int ig = lane >> 4;
    const float xlv = sh->xl, ylv = sh->yl;

    // Q = A (load ownership block): q2[ii][p] = pair (j = jg*8 + 2p, +1)
    u64 q2[8][4];
    #pragma unroll
    for (int ii = 0; ii < 8; ++ii) {
        F4U2 u0, u1;
        u0.f4 = *reinterpret_cast<const float4*>(&sh->As[AIDX(warp, ii, 0, ig, jg)]);
        u1.f4 = *reinterpret_cast<const float4*>(&sh->As[AIDX(warp, ii, 1, ig, jg)]);
        q2[ii][0] = u0.u2[0]; q2[ii][1] = u0.u2[1];
        q2[ii][2] = u1.u2[0]; q2[ii][3] = u1.u2[1];
    }
    float ym_[8];
    #pragma unroll
    for (int ii = 0; ii < 8; ++ii) ym_[ii] = sh->ymask[warp * 16 + ig * 8 + ii];

    if (tid < 128) sh->sigma[tid] = (sh->xmask[tid] > 0.f) ? 0.f : (1.f / xlv);
    __syncthreads();

    u64 sg2[4];
    {
        F4U2 sa, sb;
        sa.f4 = *reinterpret_cast<const float4*>(&sh->sigma[jg * 8]);
        sb.f4 = *reinterpret_cast<const float4*>(&sh->sigma[jg * 8 + 4]);
        sg2[0] = sa.u2[0]; sg2[1] = sa.u2[1]; sg2[2] = sb.u2[0]; sg2[3] = sb.u2[1];
    }

    // delta_0 from r = Q.sigma0
    float d_[8];
    #pragma unroll
    for (int ii = 0; ii < 8; ++ii) {
        u64 acc2 = mul2(q2[ii][0], sg2[0]);
        acc2 = fma2_(q2[ii][1], sg2[1], acc2);
        acc2 = fma2_(q2[ii][2], sg2[2], acc2);
        acc2 = fma2_(q2[ii][3], sg2[3], acc2);
        float2 pr = unpack2(acc2);
        float rv = pr.x + pr.y;
        #pragma unroll
        for (int o = 1; o < 16; o <<= 1) rv += __shfl_xor_sync(0xffffffffu, rv, o);
        d_[ii] = 1.f / (ylv * rv + ym_[ii]);
    }

    for (int t = 0; t < 50; ++t) {
        // s_j partials (from registers)
        u64 s2[4];
        #pragma unroll
        for (int p = 0; p < 4; ++p) s2[p] = pack2(0.f, 0.f);
        #pragma unroll
        for (int ii = 0; ii < 8; ++ii) {
            u64 dd = pack2(d_[ii], d_[ii]);
            #pragma unroll
            for (int p = 0; p < 4; ++p) s2[p] = fma2_(q2[ii][p], dd, s2[p]);
        }
        float s8[8];
        #pragma unroll
        for (int p = 0; p < 4; ++p) {
            float2 v = unpack2(s2[p]);
            s8[2 * p] = v.x; s8[2 * p + 1] = v.y;
        }
        #pragma unroll
        for (int e = 0; e < 8; ++e) s8[e] += __shfl_xor_sync(0xffffffffu, s8[e], 16);
        if (ig == 0) {
            *reinterpret_cast<float4*>(&sh->spartW[warp][jg * 8])
                = make_float4(s8[0], s8[1], s8[2], s8[3]);
            *reinterpret_cast<float4*>(&sh->spartW[warp][jg * 8 + 4])
                = make_float4(s8[4], s8[5], s8[6], s8[7]);
        }
        __syncthreads();
        if (tid < 128) {
            float s = 0.f;
            #pragma unroll
            for (int w8 = 0; w8 < 8; ++w8) s += sh->spartW[w8][tid];
            sh->sigma[tid] = 1.f / (xlv * s + sh->xmask[tid]);
        }
        __syncthreads();
        {
            F4U2 sa, sb;
            sa.f4 = *reinterpret_cast<const float4*>(&sh->sigma[jg * 8]);
            sb.f4 = *reinterpret_cast<const float4*>(&sh->sigma[jg * 8 + 4]);
            sg2[0] = sa.u2[0]; sg2[1] = sa.u2[1]; sg2[2] = sb.u2[0]; sg2[3] = sb.u2[1];
        }
        if (t < 49) {
            // Q <- A*delta*Q*sigma, fused with next r_i -> delta
            #pragma unroll
            for (int ii = 0; ii < 8; ++ii) {
                F4U2 a0, a1;
                a0.f4 = *reinterpret_cast<const float4*>(&sh->As[AIDX(warp, ii, 0, ig, jg)]);
                a1.f4 = *reinterpret_cast<const float4*>(&sh->As[AIDX(warp, ii, 1, ig, jg)]);
                u64 av[4] = {a0.u2[0], a0.u2[1], a1.u2[0], a1.u2[1]};
                u64 dd = pack2(d_[ii], d_[ii]);
                u64 acc2 = pack2(0.f, 0.f);
                #pragma unroll
                for (int p = 0; p < 4; ++p) {
                    u64 f  = mul2(sg2[p], dd);
                    u64 tq = mul2(av[p], q2[ii][p]);
                    q2[ii][p] = mul2(tq, f);
                    acc2 = fma2_(q2[ii][p], sg2[p], acc2);
                }
                float2 pr = unpack2(acc2);
                float rv = pr.x + pr.y;
                #pragma unroll
                for (int o = 1; o < 16; o <<= 1) rv += __shfl_xor_sync(0xffffffffu, rv, o);
                d_[ii] = 1.f / (ylv * rv + ym_[ii]);
            }
        }
    }

    // ---------------- Final: dist_b = sum cost * delta_i * Q * sigma_j --------
    float local = 0.f;
    #pragma unroll
    for (int ii = 0; ii < 8; ++ii) {
        F4U2 a0, a1;
        a0.f4 = *reinterpret_cast<const float4*>(&sh->As[AIDX(warp, ii, 0, ig, jg)]);
        a1.f4 = *reinterpret_cast<const float4*>(&sh->As[AIDX(warp, ii, 1, ig, jg)]);
        u64 av[4] = {a0.u2[0], a0.u2[1], a1.u2[0], a1.u2[1]};
        const float dl = d_[ii];
        #pragma unroll
        for (int p = 0; p < 4; ++p) {
            float2 aa = unpack2(av[p]);
            float2 qq = unpack2(q2[ii][p]);
            float2 ss = unpack2(sg2[p]);
            if (aa.x > 0.f) local += (-0.5f * __logf(aa.x)) * dl * qq.x * ss.x;
            if (aa.y > 0.f) local += (-0.5f * __logf(aa.y)) * dl * qq.y * ss.y;
        }
    }
    __syncthreads();
    sh->spart[tid] = local;
    __syncthreads();
    #pragma unroll
    for (int s = 128; s; s >>= 1) {
        if (tid < s) sh->spart[tid] += sh->spart[tid + s];
        __syncthreads();
    }
    if (tid == 0) g_dist[b] = sh->spart[0];

    // ---------------- last block reduces g_dist -> out ----------------
    __threadfence();
    if (tid == 0) sh->tick = atomicAdd(&g_count, 1u);
    __syncthreads();
    if (sh->tick == NB - 1) {
        __threadfence();
        sh->spart[tid] = g_dist[tid];
        __syncthreads();
        #pragma unroll
        for (int s = 128; s; s >>= 1) {
            if (tid < s) sh->spart[tid] += sh->spart[tid + s];
            __syncthreads();
        }
        if (tid == 0) {
            out[0] = 0.01f * sh->spart[0];
            g_count = 0;   // reset for next (graph-replayed) call
        }
    }
}

extern "C" void kernel_launch(void* const* d_in, const int* in_sizes, int n_in,
                              void* d_out, int out_size) {
    const float* txt = (const float*)d_in[0];   // entitytxt_vec [256,128,1024] f32
    const float* obj = (const float*)d_in[1];   // object_vec    [256,128,1024] f32
    const int*   tn  = (const int*)d_in[2];     // entitytxt_num [256,128] i32
    const int*   on  = (const int*)d_in[3];     // object_num    [256,128] i32

    size_t shbytes = sizeof(ShMem);
    cudaFuncSetAttribute(ot_kernel, cudaFuncAttributeMaxDynamicSharedMemorySize,
                         (int)shbytes);
    ot_kernel<<<NB, NTHREADS, shbytes>>>(txt, obj, tn, on, (float*)d_out);
}